// round 17
// baseline (speedup 1.0000x reference)
#include <cuda_runtime.h>
#include <cuda_fp16.h>
#include <math.h>
#include <stdint.h>

#define NMAX      500000
#define DIM       128
#define SNEG      256
#define STRIDE    136          // fp16 units -> 272B row stride (16B aligned, LDSM conflict-free)
#define MTILE     128          // rows per tile (16 rows per warp)
#define INV_T     10.0f
#define LOG_S     5.545177444479562f    // log(256)
#define EXSCALE   14.426950408889634f   // INV_T * log2(e), applied in f32 epilogue
#define LN2       0.6931471805599453f
#define GRIDP     444                   // persistent blocks (3 per SM)
#define MAXBLOCKS 8192

__device__ __half    g_Qn[(size_t)NMAX * DIM];
__device__ float     g_partial[MAXBLOCKS];
__device__ unsigned  g_done;

// ---------------------------------------------------------------------------
// normalize: 2 rows per warp (lanes 0-15 row0, 16-31 row1), 1KB per warp.
// ---------------------------------------------------------------------------
__global__ void normalize_kernel(const float* __restrict__ E, int n) {
    long long wid = ((blockIdx.x * (long long)blockDim.x + threadIdx.x) >> 5);
    int lane = threadIdx.x & 31;
    int h16  = lane & 15;
    long long row = wid * 2 + (lane >> 4);
    long long rowc = row < n ? row : (long long)(n - 1);

    const float4* src = reinterpret_cast<const float4*>(E + (size_t)rowc * DIM)
                      + h16 * 2;
    float4 a = src[0], b = src[1];
    float ss = a.x * a.x + a.y * a.y + a.z * a.z + a.w * a.w
             + b.x * b.x + b.y * b.y + b.z * b.z + b.w * b.w;
#pragma unroll
    for (int o = 8; o > 0; o >>= 1) ss += __shfl_xor_sync(0xffffffffu, ss, o);
    float inv = 1.0f / fmaxf(sqrtf(ss), 1e-12f);

    __half2 p0 = __floats2half2_rn(a.x * inv, a.y * inv);
    __half2 p1 = __floats2half2_rn(a.z * inv, a.w * inv);
    __half2 p2 = __floats2half2_rn(b.x * inv, b.y * inv);
    __half2 p3 = __floats2half2_rn(b.z * inv, b.w * inv);
    uint4 st;
    st.x = reinterpret_cast<unsigned&>(p0);
    st.y = reinterpret_cast<unsigned&>(p1);
    st.z = reinterpret_cast<unsigned&>(p2);
    st.w = reinterpret_cast<unsigned&>(p3);
    if (row < n)
        *reinterpret_cast<uint4*>(g_Qn + (size_t)row * DIM + h16 * 8) = st;
}

__device__ __forceinline__ float pairdot(unsigned a, unsigned b) {
    float2 fa = __half22float2(*reinterpret_cast<__half2*>(&a));
    float2 fb = __half22float2(*reinterpret_cast<__half2*>(&b));
    return fa.x * fb.x + fa.y * fb.y;
}

__device__ __forceinline__ uint32_t smem_u32(const void* p) {
    uint32_t a;
    asm("{ .reg .u64 t; cvta.to.shared.u64 t, %1; cvt.u32.u64 %0, t; }"
        : "=r"(a) : "l"(p));
    return a;
}

__device__ __forceinline__ float ex2f(float x) {
    float y;
    asm("ex2.approx.ftz.f32 %0, %1;" : "=f"(y) : "f"(x));
    return y;
}

__device__ __forceinline__ float lg2f(float x) {
    float y;
    asm("lg2.approx.ftz.f32 %0, %1;" : "=f"(y) : "f"(x));
    return y;
}

// ---------------------------------------------------------------------------
// main: persistent blocks; B staged once; per tile the pos-dot phase ALSO
// stages each warp's 16 A rows into sA (the load was already needed), so A
// fragments come from 8 ldmatrix.x4 instead of 64 scatter-LDG.
// ---------------------------------------------------------------------------
__global__ __launch_bounds__(256, 3) void main_kernel(
    const void* __restrict__ pos_idx,
    const void* __restrict__ neg_idx,
    float* __restrict__ out,
    int n, int ntiles)
{
    extern __shared__ char smem_raw[];
    __half* sV  = reinterpret_cast<__half*>(smem_raw);          // 256*136 fp16
    __half* sA  = sV + SNEG * STRIDE;                           // 128*136 fp16
    float* sPos = reinterpret_cast<float*>(sA + MTILE * STRIDE);
    float* sRed = sPos + MTILE;                                  // 8 floats
    int*   sLastP = reinterpret_cast<int*>(sRed + 8);

    const int tid  = threadIdx.x;
    const int lane = tid & 31;
    const int warp = tid >> 5;

    // ---- inline index-dtype detection (first 1KB of negatives) -------------
    int ok = 1;
    if (tid < 128) {
        long long v = ((const long long*)neg_idx)[tid];
        ok = (v >= 0 && v < (long long)n);
    }
    const int is64 = __syncthreads_and(ok);

    const int half16 = lane & 15;
    const int rsel   = lane >> 4;

    // ---- stage 256 negatives ONCE, coalesced, unscaled ----------------------
    {
#pragma unroll
        for (int i = 0; i < 16; i++) {
            int r = warp * 32 + 2 * i + rsel;
            long long vr = is64 ? ((const long long*)neg_idx)[r]
                                : (long long)((const int*)neg_idx)[r];
            uint4 v = *reinterpret_cast<const uint4*>(
                g_Qn + (size_t)vr * DIM + half16 * 8);
            *reinterpret_cast<uint4*>(sV + r * STRIDE + half16 * 8) = v;
        }
    }
    __syncthreads();

    // ldmatrix lane->row map for B (x4: two n-tiles x k lo/hi)
    const int nrow = (lane & 7) + ((lane & 16) >> 1);
    const uint32_t bAddr = smem_u32(sV) + nrow * (STRIDE * 2)
                         + ((lane & 8) << 1);
    // ldmatrix lane->addr for A (x4: rows0-7/8-15 x k lo/hi 16B)
    const uint32_t aAddr = smem_u32(sA)
                         + (warp * 16 + (lane & 15)) * (STRIDE * 2)
                         + ((lane >> 4) << 4);

    const int g  = lane >> 2;
    const int t4 = lane & 3;

    float local = 0.0f;

    for (int tile = blockIdx.x; tile < ntiles; tile += GRIDP) {
        const long long tile0 = (long long)tile * MTILE;

        // ---- pos logits + A staging: own-row load does double duty ---------
#pragma unroll
        for (int i = 0; i < 8; i++) {
            int rloc = warp * 16 + 2 * i + rsel;
            long long row = tile0 + rloc;
            float d = 0.0f;
            uint4 a = make_uint4(0u, 0u, 0u, 0u);
            if (row < n) {
                long long p = is64 ? ((const long long*)pos_idx)[row]
                                   : (long long)((const int*)pos_idx)[row];
                a = *reinterpret_cast<const uint4*>(
                    g_Qn + (size_t)row * DIM + half16 * 8);
                uint4 b = *reinterpret_cast<const uint4*>(
                    g_Qn + (size_t)p * DIM + half16 * 8);
                d = pairdot(a.x, b.x) + pairdot(a.y, b.y)
                  + pairdot(a.z, b.z) + pairdot(a.w, b.w);
            }
            *reinterpret_cast<uint4*>(sA + rloc * STRIDE + half16 * 8) = a;
#pragma unroll
            for (int o = 8; o > 0; o >>= 1)
                d += __shfl_xor_sync(0xffffffffu, d, o);
            if (half16 == 0) sPos[rloc] = d * INV_T;
        }
        __syncwarp();   // sA rows + sPos of this warp ready

        // ---- A fragments via ldmatrix from sA (8 x LDSM.x4) -----------------
        const long long rowG = tile0 + warp * 16 + g;
        unsigned afr[8][4];
#pragma unroll
        for (int k0 = 0; k0 < 8; k0++) {
            asm volatile(
                "ldmatrix.sync.aligned.m8n8.x4.shared.b16 "
                "{%0,%1,%2,%3}, [%4];"
                : "=r"(afr[k0][0]), "=r"(afr[k0][1]),
                  "=r"(afr[k0][2]), "=r"(afr[k0][3])
                : "r"(aAddr + k0 * 32));
        }

        // ---- GEMM: 8 chunks of 32 negatives, f32 accum ----------------------
        float rs0 = 0.0f, rs1 = 0.0f;
#pragma unroll
        for (int c = 0; c < 8; c++) {
            float acc[4][4];
#pragma unroll
            for (int i = 0; i < 4; i++) {
                acc[i][0] = 0.f; acc[i][1] = 0.f;
                acc[i][2] = 0.f; acc[i][3] = 0.f;
            }
#pragma unroll
            for (int k0 = 0; k0 < 8; k0++) {
#pragma unroll
                for (int nt2 = 0; nt2 < 2; nt2++) {
                    unsigned b0, b1, b2, b3;
                    uint32_t a = bAddr + (c * 32 + nt2 * 16) * (STRIDE * 2)
                               + k0 * 32;
                    asm volatile(
                        "ldmatrix.sync.aligned.m8n8.x4.shared.b16 "
                        "{%0,%1,%2,%3}, [%4];"
                        : "=r"(b0), "=r"(b1), "=r"(b2), "=r"(b3) : "r"(a));
                    asm volatile(
                        "mma.sync.aligned.m16n8k16.row.col.f32.f16.f16.f32 "
                        "{%0,%1,%2,%3}, {%4,%5,%6,%7}, {%8,%9}, {%0,%1,%2,%3};\n"
                        : "+f"(acc[nt2 * 2][0]), "+f"(acc[nt2 * 2][1]),
                          "+f"(acc[nt2 * 2][2]), "+f"(acc[nt2 * 2][3])
                        : "r"(afr[k0][0]), "r"(afr[k0][1]),
                          "r"(afr[k0][2]), "r"(afr[k0][3]),
                          "r"(b0), "r"(b1));
                    asm volatile(
                        "mma.sync.aligned.m16n8k16.row.col.f32.f16.f16.f32 "
                        "{%0,%1,%2,%3}, {%4,%5,%6,%7}, {%8,%9}, {%0,%1,%2,%3};\n"
                        : "+f"(acc[nt2 * 2 + 1][0]), "+f"(acc[nt2 * 2 + 1][1]),
                          "+f"(acc[nt2 * 2 + 1][2]), "+f"(acc[nt2 * 2 + 1][3])
                        : "r"(afr[k0][0]), "r"(afr[k0][1]),
                          "r"(afr[k0][2]), "r"(afr[k0][3]),
                          "r"(b2), "r"(b3));
                }
            }
            // epilogue: logits = dot*10; exp via ex2(dot * 10*log2e)
#pragma unroll
            for (int nt = 0; nt < 4; nt++) {
                rs0 += ex2f(acc[nt][0] * EXSCALE) + ex2f(acc[nt][1] * EXSCALE);
                rs1 += ex2f(acc[nt][2] * EXSCALE) + ex2f(acc[nt][3] * EXSCALE);
            }
        }

        rs0 += __shfl_xor_sync(0xffffffffu, rs0, 1);
        rs0 += __shfl_xor_sync(0xffffffffu, rs0, 2);
        rs1 += __shfl_xor_sync(0xffffffffu, rs1, 1);
        rs1 += __shfl_xor_sync(0xffffffffu, rs1, 2);

        if (t4 == 0) {
            if (rowG < n)
                local += sPos[warp * 16 + g]     - (lg2f(rs0) * LN2 - LOG_S);
            if (rowG + 8 < n)
                local += sPos[warp * 16 + g + 8] - (lg2f(rs1) * LN2 - LOG_S);
        }
        __syncwarp();   // sA reads done before next tile overwrites
    }

    // ---- deterministic block + grid reduction -------------------------------
#pragma unroll
    for (int o = 16; o > 0; o >>= 1)
        local += __shfl_xor_sync(0xffffffffu, local, o);
    if (lane == 0) sRed[warp] = local;
    __syncthreads();

    if (tid == 0) {
        float s = 0.0f;
#pragma unroll
        for (int w = 0; w < 8; w++) s += sRed[w];
        g_partial[blockIdx.x] = s;
        __threadfence();
        unsigned t = atomicAdd(&g_done, 1u);
        *sLastP = (t == (unsigned)(GRIDP - 1));
    }
    __syncthreads();
    if (*sLastP) {
        float s = 0.0f;
        for (int i = tid; i < GRIDP; i += 256) s += g_partial[i];
#pragma unroll
        for (int o = 16; o > 0; o >>= 1)
            s += __shfl_xor_sync(0xffffffffu, s, o);
        if (lane == 0) sRed[warp] = s;
        __syncthreads();
        if (tid == 0) {
            float tot = 0.f;
#pragma unroll
            for (int w = 0; w < 8; w++) tot += sRed[w];
            out[0] = -tot / (float)n;
            g_done = 0;                  // reset for next graph replay
        }
    }
}

// ---------------------------------------------------------------------------
extern "C" void kernel_launch(void* const* d_in, const int* in_sizes, int n_in,
                              void* d_out, int out_size) {
    const float* E   = (const float*)d_in[0];
    const void*  pos = d_in[1];
    const void*  neg = d_in[2];
    int n = in_sizes[1];   // number of edges

    int nblk_norm = (n + 15) / 16;   // 8 warps/block, 2 rows/warp
    normalize_kernel<<<nblk_norm, 256>>>(E, n);

    int ntiles = (n + MTILE - 1) / MTILE;
    size_t smem = (size_t)((SNEG + MTILE) * STRIDE) * sizeof(__half)
                + (size_t)(MTILE + 8 + 4) * sizeof(float);
    cudaFuncSetAttribute(main_kernel,
                         cudaFuncAttributeMaxDynamicSharedMemorySize, (int)smem);
    main_kernel<<<GRIDP, 256, smem>>>(pos, neg, (float*)d_out, n, ntiles);
}